// round 15
// baseline (speedup 1.0000x reference)
#include <cuda_runtime.h>
#include <cuda_fp16.h>
#include <math.h>
#include <stdint.h>

// Problem constants
#define BB 2
#define TT 4096
#define CC 2048
#define HH 16
#define DD 128
#define KK 4
#define NTOK (BB*TT)          // 8192 tokens
#define NTOT (BB*TT*CC)       // 16777216 elements
#define NCH  32               // scan chunks
#define CHL  (TT/NCH)         // 128 timesteps per chunk

// ---------------- scratch (device globals: allocation-free) ----------------
__device__ float g_xc[NTOT];      // conv+silu output (fp32, feeds gamma GEMM)
__device__ float g_q [NTOT];      // q (L2-normalized in GEMM epilogue)
__device__ float g_k [NTOT];      // k (L2-normalized in GEMM epilogue)
__device__ float g_v [NTOT];      // v (LayerNormed) -> local mem (in place)
__device__ float g_ig[NTOT];
__device__ float g_og[NTOT];
__device__ float g_gamma[NTOK*HH];
__device__ float g_cumG[BB*HH*TT];          // per-chunk cumulative gamma
__device__ float g_carry[BB*HH*NCH*DD];     // chunk-final local mem
__device__ float g_prefix[BB*HH*NCH*DD];    // incoming prefix per chunk

// fp16 buffers (hi-only; A-rounding dominates the error budget)
__device__ __half g_xh[NTOT];               // x
__device__ __half g_ch[NTOT];               // xc
__device__ __half g_oh[NTOT];               // gated output
__device__ __half g_wh[6*CC*CC];            // Wq,Wk,Wv,ig_w,og_w,Wo

// ---------------- helpers ----------------
__device__ __forceinline__ float warp_sum(float v) {
#pragma unroll
    for (int o = 16; o; o >>= 1) v += __shfl_xor_sync(0xFFFFFFFFu, v, o);
    return v;
}
__device__ __forceinline__ float sigmoidf(float x) { return 1.f / (1.f + expf(-x)); }

__device__ __forceinline__ uint32_t smem_u32(const void* p) {
    uint32_t a;
    asm("{ .reg .u64 t; cvta.to.shared.u64 t, %1; cvt.u32.u64 %0, t; }" : "=r"(a) : "l"(p));
    return a;
}
__device__ __forceinline__ void cp16(uint32_t dst, const void* src) {
    asm volatile("cp.async.cg.shared.global [%0], [%1], 16;" :: "r"(dst), "l"(src));
}
#define CP_COMMIT() asm volatile("cp.async.commit_group;" ::: "memory")
template <int N>
__device__ __forceinline__ void cp_wait() { asm volatile("cp.async.wait_group %0;" :: "n"(N) : "memory"); }

__device__ __forceinline__ void ldsm4(uint32_t* r, uint32_t addr) {
    asm volatile("ldmatrix.sync.aligned.m8n8.x4.shared.b16 {%0,%1,%2,%3}, [%4];"
                 : "=r"(r[0]), "=r"(r[1]), "=r"(r[2]), "=r"(r[3]) : "r"(addr));
}
__device__ __forceinline__ void mma_f16(float* c, const uint32_t* a, const uint32_t* b) {
    asm volatile(
        "mma.sync.aligned.m16n8k16.row.col.f32.f16.f16.f32 "
        "{%0,%1,%2,%3}, {%4,%5,%6,%7}, {%8,%9}, {%0,%1,%2,%3};"
        : "+f"(c[0]), "+f"(c[1]), "+f"(c[2]), "+f"(c[3])
        : "r"(a[0]), "r"(a[1]), "r"(a[2]), "r"(a[3]), "r"(b[0]), "r"(b[1]));
}

// cast all 6 weight matrices to fp16 in one launch
__global__ void cvt_w_kernel(const float* __restrict__ w0, const float* __restrict__ w1,
                             const float* __restrict__ w2, const float* __restrict__ w3,
                             const float* __restrict__ w4, const float* __restrict__ w5) {
    int i = blockIdx.x * blockDim.x + threadIdx.x;           // 0 .. 6*WSZ-1
    const int WSZ = CC * CC;
    int j = i / WSZ, r = i - j * WSZ;
    const float* src = j == 0 ? w0 : j == 1 ? w1 : j == 2 ? w2 : j == 3 ? w3 : j == 4 ? w4 : w5;
    g_wh[i] = __float2half(src[r]);
}

// ---------------- fp16 HMMA GEMM (single product): C = A @ W^T --------------
// CTA tile 128x128, BK=32, 4 warps (2x2), warp tile 64x64, 4-stage cp.async,
// 128 threads, 2 CTAs/SM. Rows: 64B data + 16B pad (ROWA=80).
// EPI: 0 = plain, 1 = sigmoid(x+bias), 2 = qkv (sel 0,1: L2 norm; sel 2: LN).
// M offset mbase allows token-sliced launches (post/Wo pipelining).
#define BKK     32
#define ROWA    80
#define ATILE_B (128*ROWA)         // 10240
#define STAGEB  (2*ATILE_B)        // 20480 (A + B)
#define STAGES  4
#define KTILES  (CC/BKK)           // 64
#define GEMM_SMEM (STAGES*STAGEB)  // 81920

template <int EPI>
__global__ void __launch_bounds__(128, 2)
gemm_multi(const __half* __restrict__ Ah,
           const __half* __restrict__ B0, const __half* __restrict__ B1,
           const __half* __restrict__ B2,
           float* __restrict__ C0, float* __restrict__ C1, float* __restrict__ C2,
           const float* __restrict__ bias0, const float* __restrict__ bias1,
           int mbase)
{
    extern __shared__ char smem[];
    const uint32_t sb = smem_u32(smem);
    const int sel = blockIdx.x >> 4;
    const __half* Bm = sel == 0 ? B0 : sel == 1 ? B1 : B2;
    float* C = sel == 0 ? C0 : sel == 1 ? C1 : C2;

    const int tid = threadIdx.x;
    const int lane = tid & 31;
    const int wid = tid >> 5;
    const int bm = mbase + blockIdx.y * 128;
    const int bn = (blockIdx.x & 15) * 128;
    const int wm = (wid >> 1) * 64;   // 0 or 64
    const int wn = (wid & 1) * 64;    // 0 or 64

    float acc[4][8][4];
#pragma unroll
    for (int i = 0; i < 4; i++)
#pragma unroll
        for (int j = 0; j < 8; j++)
#pragma unroll
            for (int r = 0; r < 4; r++) acc[i][j][r] = 0.f;

    // ldmatrix per-thread address components
    const int arow = lane & 15;
    const uint32_t ahalf = (uint32_t)((lane >> 4) << 4);        // 0 or 16
    const int brow = (lane & 7) | ((lane >> 4) << 3);
    const uint32_t bhalf = (uint32_t)(((lane >> 3) & 1) << 4);  // 0 or 16

    auto load_stage = [&](int s, int kt) {
        uint32_t base = sb + s * STAGEB;
        int k0 = kt * BKK;
#pragma unroll
        for (int i = 0; i < 4; i++) {
            int u = tid + i * 128;          // 0..511
            int r = u >> 2, c = u & 3;
            cp16(base + r * ROWA + c * 16, Ah + (size_t)(bm + r) * CC + k0 + c * 8);
        }
#pragma unroll
        for (int i = 0; i < 4; i++) {
            int u = tid + i * 128;          // 0..511
            int r = u >> 2, c = u & 3;
            cp16(base + ATILE_B + r * ROWA + c * 16, Bm + (size_t)(bn + r) * CC + k0 + c * 8);
        }
    };

    load_stage(0, 0); CP_COMMIT();
    load_stage(1, 1); CP_COMMIT();
    load_stage(2, 2); CP_COMMIT();

    for (int kt = 0; kt < KTILES; kt++) {
        if (kt <= KTILES - 3)      cp_wait<2>();
        else if (kt == KTILES - 2) cp_wait<1>();
        else                       cp_wait<0>();
        __syncthreads();
        if (kt + 3 < KTILES) { load_stage((kt + 3) % STAGES, kt + 3); CP_COMMIT(); }

        const uint32_t st = sb + (kt % STAGES) * STAGEB;
        const uint32_t aBase = st + (uint32_t)((wm + arow) * ROWA);
        const uint32_t bBase = st + ATILE_B + (uint32_t)((wn + brow) * ROWA);
#pragma unroll
        for (int ks = 0; ks < 2; ks++) {
            uint32_t ah[4][4];
            const uint32_t aoff = (uint32_t)(ks * 32) + ahalf;
#pragma unroll
            for (int mi = 0; mi < 4; mi++)
                ldsm4(ah[mi], aBase + mi * 16 * ROWA + aoff);
            const uint32_t boff = (uint32_t)(ks * 32) + bhalf;
#pragma unroll
            for (int jj = 0; jj < 4; jj++) {
                uint32_t bh[4];
                ldsm4(bh, bBase + jj * 16 * ROWA + boff);
#pragma unroll
                for (int mi = 0; mi < 4; mi++) {
                    mma_f16(acc[mi][2*jj],   ah[mi], bh);
                    mma_f16(acc[mi][2*jj+1], ah[mi], bh + 2);
                }
            }
        }
    }

    const int gr = lane >> 2, ti = lane & 3;

    if (EPI == 2) {
        // fused row-norm epilogue: per-row sum/sumsq over the 128-col tile
        float rs[8], rq[8];
#pragma unroll
        for (int mi = 0; mi < 4; mi++) {
#pragma unroll
            for (int half = 0; half < 2; half++) {
                float s = 0.f, ss = 0.f;
#pragma unroll
                for (int j = 0; j < 8; j++) {
                    float a0 = acc[mi][j][half*2+0], a1 = acc[mi][j][half*2+1];
                    s += a0 + a1; ss += a0*a0 + a1*a1;
                }
                rs[mi*2+half] = s; rq[mi*2+half] = ss;
            }
        }
#pragma unroll
        for (int o = 1; o <= 2; o <<= 1) {
#pragma unroll
            for (int t = 0; t < 8; t++) {
                rs[t] += __shfl_xor_sync(0xFFFFFFFFu, rs[t], o);
                rq[t] += __shfl_xor_sync(0xFFFFFFFFu, rq[t], o);
            }
        }
        float* ssum = (float*)smem;         // [128][2]
        float* sss  = ssum + 256;           // [128][2]
        __syncthreads();
        if (ti == 0) {
#pragma unroll
            for (int t = 0; t < 8; t++) {
                int row = wm + (t >> 1) * 16 + (t & 1) * 8 + gr;
                int wc = wid & 1;
                ssum[row * 2 + wc] = rs[t];
                sss [row * 2 + wc] = rq[t];
            }
        }
        __syncthreads();
#pragma unroll
        for (int mi = 0; mi < 4; mi++) {
#pragma unroll
            for (int half = 0; half < 2; half++) {
                int row = wm + mi * 16 + half * 8 + gr;
                int m0 = bm + row;
                float S = ssum[row*2] + ssum[row*2+1];
                float Q = sss [row*2] + sss [row*2+1];
                if (sel < 2) {
                    float inv = 1.f / fmaxf(sqrtf(Q), 1e-12f);
#pragma unroll
                    for (int j = 0; j < 8; j++) {
                        int col = bn + wn + j * 8 + ti * 2;
                        float2 v = make_float2(acc[mi][j][half*2] * inv,
                                               acc[mi][j][half*2+1] * inv);
                        *(float2*)(C + (size_t)m0 * CC + col) = v;
                    }
                } else {
                    float mean = S * (1.f / 128.f);
                    float rr = rsqrtf(Q * (1.f / 128.f) - mean * mean + 1e-5f);
#pragma unroll
                    for (int j = 0; j < 8; j++) {
                        int d = wn + j * 8 + ti * 2;
                        int col = bn + d;
                        float2 v;
                        v.x = (acc[mi][j][half*2]   - mean) * rr * bias0[d]   + bias1[d];
                        v.y = (acc[mi][j][half*2+1] - mean) * rr * bias0[d+1] + bias1[d+1];
                        *(float2*)(C + (size_t)m0 * CC + col) = v;
                    }
                }
            }
        }
    } else {
        const float* bias = (sel == 0) ? bias0 : bias1;
#pragma unroll
        for (int mi = 0; mi < 4; mi++) {
            int m0 = bm + wm + mi * 16 + gr;
#pragma unroll
            for (int j = 0; j < 8; j++) {
                int col = bn + wn + j * 8 + ti * 2;
                float2 v0 = make_float2(acc[mi][j][0], acc[mi][j][1]);
                float2 v1 = make_float2(acc[mi][j][2], acc[mi][j][3]);
                if (EPI == 1) {
                    float b0 = bias[col], b1 = bias[col + 1];
                    v0.x = sigmoidf(v0.x + b0); v0.y = sigmoidf(v0.y + b1);
                    v1.x = sigmoidf(v1.x + b0); v1.y = sigmoidf(v1.y + b1);
                }
                *(float2*)(C + (size_t)m0 * CC + col) = v0;
                *(float2*)(C + (size_t)(m0 + 8) * CC + col) = v1;
            }
        }
    }
}

// ------- causal depthwise conv (K=4) + SiLU + fp16 casts (xc and x) --------
__global__ void conv_silu_kernel(const float* __restrict__ x,
                                 const float* __restrict__ w,
                                 const float* __restrict__ b) {
    int idx = blockIdx.x * blockDim.x + threadIdx.x;
    if (idx >= NTOT) return;
    int c = idx & (CC - 1);
    int t = (idx / CC) & (TT - 1);
    float acc = b[c];
    const float* wc = w + c * KK;
    float xcur = 0.f;
#pragma unroll
    for (int j = 0; j < KK; j++) {
        int tt = t - (KK - 1) + j;
        if (tt >= 0) {
            float xv = x[idx + (j - (KK - 1)) * CC];
            if (j == KK - 1) xcur = xv;
            acc = fmaf(xv, wc[j], acc);
        }
    }
    float y = acc * sigmoidf(acc);
    g_xc[idx] = y;
    g_ch[idx] = __float2half(y);
    g_xh[idx] = __float2half(xcur);
}

// ------- gamma = sigmoid(xc @ gamma_w^T + gamma_b): 8 tokens per block -----
__global__ void gamma_kernel(const float* __restrict__ gw, const float* __restrict__ gb) {
    extern __shared__ float sx[];   // 8*CC floats = 64KB
    int t0 = blockIdx.x * 8;
    for (int i = threadIdx.x; i < 8 * CC; i += 256)
        sx[i] = g_xc[(size_t)t0 * CC + i];
    __syncthreads();
    int warp = threadIdx.x >> 5, lane = threadIdx.x & 31;   // warp = token
    const float* xr = sx + warp * CC;
#pragma unroll
    for (int h = 0; h < HH; h++) {
        const float* w = gw + (size_t)h * CC;
        float s = 0.f;
        for (int k = lane; k < CC; k += 32) s = fmaf(xr[k], w[k], s);
        s = warp_sum(s);
        if (lane == 0) g_gamma[(size_t)(t0 + warp) * HH + h] = sigmoidf(s + gb[h]);
    }
}

// ------- chunked scan pass A: kv = ig*k*v inline + local scan --------------
__global__ void scan_local_kernel() {
    int blk = blockIdx.x;
    int chunk = blk & (NCH - 1);
    int bh = blk / NCH;
    int b = bh / HH, h = bh % HH;
    int d = threadIdx.x;
    int t0 = chunk * CHL;
    size_t idx = ((size_t)(b * TT + t0) * HH + h) * DD + d;
    const float* gam = g_gamma + (size_t)(b * TT + t0) * HH + h;
    float* cumg = g_cumG + (size_t)bh * TT + t0;
    float mem = 0.f, cg = 1.f;
#pragma unroll 4
    for (int tt = 0; tt < CHL; tt++) {
        float g = __ldg(gam + (size_t)tt * HH);
        float kv = g_ig[idx] * g_k[idx] * g_v[idx];
        mem = fmaf(g, mem, kv);
        g_v[idx] = mem;
        cg *= g;
        if (d == 0) cumg[tt] = cg;
        idx += (size_t)HH * DD;
    }
    g_carry[(size_t)blk * DD + d] = mem;
}

// ---------------- chunked scan: pass B (combine carries) -------------------
__global__ void scan_carry_kernel() {
    int bh = blockIdx.x;
    int d = threadIdx.x;
    float p = 0.f;
    for (int c = 0; c < NCH; c++) {
        g_prefix[((size_t)bh * NCH + c) * DD + d] = p;
        float G = g_cumG[(size_t)bh * TT + c * CHL + CHL - 1];
        p = g_carry[((size_t)bh * NCH + c) * DD + d] + G * p;
    }
}

// -------- prefix apply + LN(mem)*q -> GroupNorm -> *og -> fp16 cast --------
// row0 = starting (b,t,h) row for token-sliced launches.
__global__ void post_kernel(const float* __restrict__ mn_g, const float* __restrict__ mn_b,
                            const float* __restrict__ gn_g, const float* __restrict__ gn_b,
                            int row0) {
    int row = row0 + ((blockIdx.x * blockDim.x + threadIdx.x) >> 5);
    int lane = threadIdx.x & 31;
    if (row >= NTOK * HH) return;
    size_t off = (size_t)row * DD + lane * 4;
    float4 m  = *(const float4*)(g_v + off);
    float4 q  = *(const float4*)(g_q + off);
    float4 og = *(const float4*)(g_og + off);

    int b = row / (TT * HH);
    int t = (row / HH) & (TT - 1);
    int h = row & (HH - 1);
    int bh = b * HH + h;
    int chunk = t / CHL;
    float cg = g_cumG[(size_t)bh * TT + t];
    float4 pf = *(const float4*)(g_prefix + ((size_t)bh * NCH + chunk) * DD + lane * 4);
    m.x = fmaf(pf.x, cg, m.x);
    m.y = fmaf(pf.y, cg, m.y);
    m.z = fmaf(pf.z, cg, m.z);
    m.w = fmaf(pf.w, cg, m.w);

    float s = m.x + m.y + m.z + m.w;
    float ss = m.x * m.x + m.y * m.y + m.z * m.z + m.w * m.w;
    s = warp_sum(s); ss = warp_sum(ss);
    float mean = s * (1.f / DD);
    float var = ss * (1.f / DD) - mean * mean;
    float r = rsqrtf(var + 1e-5f);
    int d = lane * 4;
    float4 o1;
    o1.x = ((m.x - mean) * r * mn_g[d + 0] + mn_b[d + 0]) * q.x;
    o1.y = ((m.y - mean) * r * mn_g[d + 1] + mn_b[d + 1]) * q.y;
    o1.z = ((m.z - mean) * r * mn_g[d + 2] + mn_b[d + 2]) * q.z;
    o1.w = ((m.w - mean) * r * mn_g[d + 3] + mn_b[d + 3]) * q.w;

    float s2 = o1.x + o1.y + o1.z + o1.w;
    float ss2 = o1.x * o1.x + o1.y * o1.y + o1.z * o1.z + o1.w * o1.w;
    s2 = warp_sum(s2); ss2 = warp_sum(ss2);
    float mean2 = s2 * (1.f / DD);
    float var2 = ss2 * (1.f / DD) - mean2 * mean2;
    float r2 = rsqrtf(var2 + 1e-5f);
    int c = h * DD + d;
    float ov0 = (((o1.x - mean2) * r2) * gn_g[c + 0] + gn_b[c + 0]) * og.x;
    float ov1 = (((o1.y - mean2) * r2) * gn_g[c + 1] + gn_b[c + 1]) * og.y;
    float ov2 = (((o1.z - mean2) * r2) * gn_g[c + 2] + gn_b[c + 2]) * og.z;
    float ov3 = (((o1.w - mean2) * r2) * gn_g[c + 3] + gn_b[c + 3]) * og.w;
    __half2* dst = (__half2*)(g_oh + off);
    dst[0] = __floats2half2_rn(ov0, ov1);
    dst[1] = __floats2half2_rn(ov2, ov3);
}

// ---------------- launch ----------------------------------------------------
extern "C" void kernel_launch(void* const* d_in, const int* in_sizes, int n_in,
                              void* d_out, int out_size) {
    const float* x       = (const float*)d_in[0];
    const float* Wq      = (const float*)d_in[1];
    const float* Wk      = (const float*)d_in[2];
    const float* Wv      = (const float*)d_in[3];
    const float* Wo      = (const float*)d_in[4];
    const float* conv_w  = (const float*)d_in[5];
    const float* conv_b  = (const float*)d_in[6];
    const float* ig_w    = (const float*)d_in[7];
    const float* ig_b    = (const float*)d_in[8];
    const float* og_w    = (const float*)d_in[9];
    const float* og_b    = (const float*)d_in[10];
    const float* gamma_w = (const float*)d_in[11];
    const float* gamma_b = (const float*)d_in[12];
    const float* vn_g    = (const float*)d_in[13];
    const float* vn_b    = (const float*)d_in[14];
    const float* gn_g    = (const float*)d_in[15];
    const float* gn_b    = (const float*)d_in[16];
    const float* mn_g    = (const float*)d_in[17];
    const float* mn_b    = (const float*)d_in[18];
    float* out = (float*)d_out;

    float *p_q, *p_k, *p_v, *p_ig, *p_og;
    cudaGetSymbolAddress((void**)&p_q,  g_q);
    cudaGetSymbolAddress((void**)&p_k,  g_k);
    cudaGetSymbolAddress((void**)&p_v,  g_v);
    cudaGetSymbolAddress((void**)&p_ig, g_ig);
    cudaGetSymbolAddress((void**)&p_og, g_og);

    __half *p_xh, *p_ch, *p_oh, *p_wh;
    cudaGetSymbolAddress((void**)&p_xh, g_xh);
    cudaGetSymbolAddress((void**)&p_ch, g_ch);
    cudaGetSymbolAddress((void**)&p_oh, g_oh);
    cudaGetSymbolAddress((void**)&p_wh, g_wh);

    cudaFuncSetAttribute((const void*)gemm_multi<0>, cudaFuncAttributeMaxDynamicSharedMemorySize, GEMM_SMEM);
    cudaFuncSetAttribute((const void*)gemm_multi<1>, cudaFuncAttributeMaxDynamicSharedMemorySize, GEMM_SMEM);
    cudaFuncSetAttribute((const void*)gemm_multi<2>, cudaFuncAttributeMaxDynamicSharedMemorySize, GEMM_SMEM);
    cudaFuncSetAttribute(gamma_kernel, cudaFuncAttributeMaxDynamicSharedMemorySize, 8 * CC * 4);

    const size_t WSZ = (size_t)CC * CC;   // 4M elems per weight matrix

    // side stream + events for forked capture (created per call; few calls)
    cudaStream_t s1;
    cudaStreamCreateWithFlags(&s1, cudaStreamNonBlocking);
    cudaEvent_t e0, eW, eConv, eJoin, ePost0, eWo0;
    cudaEventCreateWithFlags(&e0,    cudaEventDisableTiming);
    cudaEventCreateWithFlags(&eW,    cudaEventDisableTiming);
    cudaEventCreateWithFlags(&eConv, cudaEventDisableTiming);
    cudaEventCreateWithFlags(&eJoin, cudaEventDisableTiming);
    cudaEventCreateWithFlags(&ePost0, cudaEventDisableTiming);
    cudaEventCreateWithFlags(&eWo0,  cudaEventDisableTiming);

    // fork: cvt_w on s1 parallel with conv on default stream
    cudaEventRecord(e0, 0);
    cudaStreamWaitEvent(s1, e0, 0);
    cvt_w_kernel<<<(6 * (int)WSZ) / 256, 256, 0, s1>>>(Wq, Wk, Wv, ig_w, og_w, Wo);
    cudaEventRecord(eW, s1);

    conv_silu_kernel<<<NTOT / 256, 256>>>(x, conv_w, conv_b);
    cudaEventRecord(eConv, 0);

    // qkv on stream 0 (needs conv + cvt_w)
    cudaStreamWaitEvent(0, eW, 0);
    {
        dim3 grid(48, NTOK / 128);
        gemm_multi<2><<<grid, 128, GEMM_SMEM>>>(p_xh,
            p_wh + 0*WSZ, p_wh + 1*WSZ, p_wh + 2*WSZ,
            p_q, p_k, p_v, vn_g, vn_b, 0);
    }

    // gamma first on s1 (only needs conv), then ig/og — both overlap qkv
    cudaStreamWaitEvent(s1, eConv, 0);
    gamma_kernel<<<NTOK / 8, 256, 8 * CC * 4, s1>>>(gamma_w, gamma_b);
    {
        dim3 grid(32, NTOK / 128);
        gemm_multi<1><<<grid, 128, GEMM_SMEM, s1>>>(p_ch,
            p_wh + 3*WSZ, p_wh + 4*WSZ, p_wh + 4*WSZ,
            p_ig, p_og, p_og, ig_b, og_b, 0);
    }
    cudaEventRecord(eJoin, s1);
    cudaStreamWaitEvent(0, eJoin, 0);

    scan_local_kernel<<<BB * HH * NCH, DD>>>();
    scan_carry_kernel<<<BB * HH, DD>>>();

    // post/Wo pipelined in two token halves:
    //   s0: post(half0) -> Wo(half0)
    //   s1: post(half1) (overlaps Wo(half0)) -> s0: Wo(half1)
    int halfrows = (NTOK * HH) / 2;              // 65536 (b=0)
    int hblocks = halfrows / 8;                  // 8192 blocks of 256 thr
    post_kernel<<<hblocks, 256>>>(mn_g, mn_b, gn_g, gn_b, 0);
    cudaEventRecord(ePost0, 0);

    cudaStreamWaitEvent(s1, ePost0, 0);          // also orders scan results for s1
    post_kernel<<<hblocks, 256, 0, s1>>>(mn_g, mn_b, gn_g, gn_b, halfrows);
    cudaEventRecord(eJoin, s1);

    {
        dim3 grid(16, (NTOK / 2) / 128);         // 16 x 32
        gemm_multi<0><<<grid, 128, GEMM_SMEM>>>(p_oh,
            p_wh + 5*WSZ, p_wh + 5*WSZ, p_wh + 5*WSZ,
            out, out, out, nullptr, nullptr, 0);
        cudaStreamWaitEvent(0, eJoin, 0);
        gemm_multi<0><<<grid, 128, GEMM_SMEM>>>(p_oh,
            p_wh + 5*WSZ, p_wh + 5*WSZ, p_wh + 5*WSZ,
            out, out, out, nullptr, nullptr, NTOK / 2);
    }
}

// round 16
// speedup vs baseline: 1.0719x; 1.0719x over previous
#include <cuda_runtime.h>
#include <cuda_fp16.h>
#include <math.h>
#include <stdint.h>

// Problem constants
#define BB 2
#define TT 4096
#define CC 2048
#define HH 16
#define DD 128
#define KK 4
#define NTOK (BB*TT)          // 8192 tokens
#define NTOT (BB*TT*CC)       // 16777216 elements
#define NCH  32               // scan chunks
#define CHL  (TT/NCH)         // 128 timesteps per chunk

// ---------------- scratch (device globals: allocation-free) ----------------
__device__ float g_q [NTOT];      // q (L2-normalized in GEMM epilogue)
__device__ float g_k [NTOT];      // k (L2-normalized in GEMM epilogue)
__device__ float g_v [NTOT];      // v (LayerNormed) -> local mem (in place)
__device__ float g_ig[NTOT];
__device__ float g_og[NTOT];
__device__ float g_gamma[NTOK*HH];
__device__ float g_cumG[BB*HH*TT];          // per-chunk cumulative gamma
__device__ float g_carry[BB*HH*NCH*DD];     // chunk-final local mem
__device__ float g_prefix[BB*HH*NCH*DD];    // incoming prefix per chunk

// fp16 buffers (hi-only; A-rounding dominates the error budget)
__device__ __half g_xh[NTOT];               // x
__device__ __half g_ch[NTOT];               // xc
__device__ __half g_oh[NTOT];               // gated output
__device__ __half g_wh[6*CC*CC];            // Wq,Wk,Wv,ig_w,og_w,Wo
__device__ __half g_gwpad[128*CC];          // gamma_w zero-padded to 128 rows

// ---------------- helpers ----------------
__device__ __forceinline__ float warp_sum(float v) {
#pragma unroll
    for (int o = 16; o; o >>= 1) v += __shfl_xor_sync(0xFFFFFFFFu, v, o);
    return v;
}
__device__ __forceinline__ float sigmoidf(float x) { return 1.f / (1.f + expf(-x)); }

__device__ __forceinline__ uint32_t smem_u32(const void* p) {
    uint32_t a;
    asm("{ .reg .u64 t; cvta.to.shared.u64 t, %1; cvt.u32.u64 %0, t; }" : "=r"(a) : "l"(p));
    return a;
}
__device__ __forceinline__ void cp16(uint32_t dst, const void* src) {
    asm volatile("cp.async.cg.shared.global [%0], [%1], 16;" :: "r"(dst), "l"(src));
}
#define CP_COMMIT() asm volatile("cp.async.commit_group;" ::: "memory")
template <int N>
__device__ __forceinline__ void cp_wait() { asm volatile("cp.async.wait_group %0;" :: "n"(N) : "memory"); }

__device__ __forceinline__ void ldsm4(uint32_t* r, uint32_t addr) {
    asm volatile("ldmatrix.sync.aligned.m8n8.x4.shared.b16 {%0,%1,%2,%3}, [%4];"
                 : "=r"(r[0]), "=r"(r[1]), "=r"(r[2]), "=r"(r[3]) : "r"(addr));
}
__device__ __forceinline__ void mma_f16(float* c, const uint32_t* a, const uint32_t* b) {
    asm volatile(
        "mma.sync.aligned.m16n8k16.row.col.f32.f16.f16.f32 "
        "{%0,%1,%2,%3}, {%4,%5,%6,%7}, {%8,%9}, {%0,%1,%2,%3};"
        : "+f"(c[0]), "+f"(c[1]), "+f"(c[2]), "+f"(c[3])
        : "r"(a[0]), "r"(a[1]), "r"(a[2]), "r"(a[3]), "r"(b[0]), "r"(b[1]));
}

// cast all 6 weight matrices to fp16 in one launch
__global__ void cvt_w_kernel(const float* __restrict__ w0, const float* __restrict__ w1,
                             const float* __restrict__ w2, const float* __restrict__ w3,
                             const float* __restrict__ w4, const float* __restrict__ w5) {
    int i = blockIdx.x * blockDim.x + threadIdx.x;           // 0 .. 6*WSZ-1
    const int WSZ = CC * CC;
    int j = i / WSZ, r = i - j * WSZ;
    const float* src = j == 0 ? w0 : j == 1 ? w1 : j == 2 ? w2 : j == 3 ? w3 : j == 4 ? w4 : w5;
    g_wh[i] = __float2half(src[r]);
}

// gamma_w [16,2048] -> zero-padded fp16 [128,2048]
__global__ void cvt_gw_kernel(const float* __restrict__ gw) {
    int i = blockIdx.x * blockDim.x + threadIdx.x;           // 0 .. 128*CC-1
    int row = i >> 11;
    g_gwpad[i] = __float2half(row < HH ? gw[i] : 0.f);
}

// ---------------- fp16 HMMA GEMM (single product): C = A @ W^T --------------
// CTA tile 128x128, BK=32, 4 warps (2x2), warp tile 64x64, 4-stage cp.async,
// 128 threads, 2 CTAs/SM. Rows: 64B data + 16B pad (ROWA=80).
// EPI: 0 = plain, 1 = sigmoid(x+bias) [sel==2 -> gamma tile, writes g_gamma],
//      2 = qkv (sel 0,1: L2 norm; sel 2: LayerNorm via bias0/bias1).
#define BKK     32
#define ROWA    80
#define ATILE_B (128*ROWA)         // 10240
#define STAGEB  (2*ATILE_B)        // 20480 (A + B)
#define STAGES  4
#define KTILES  (CC/BKK)           // 64
#define GEMM_SMEM (STAGES*STAGEB)  // 81920

template <int EPI>
__global__ void __launch_bounds__(128, 2)
gemm_multi(const __half* __restrict__ Ah,
           const __half* __restrict__ B0, const __half* __restrict__ B1,
           const __half* __restrict__ B2,
           float* __restrict__ C0, float* __restrict__ C1, float* __restrict__ C2,
           const float* __restrict__ bias0, const float* __restrict__ bias1,
           const float* __restrict__ bias2)
{
    extern __shared__ char smem[];
    const uint32_t sb = smem_u32(smem);
    const int sel = blockIdx.x >> 4;
    const __half* Bm = sel == 0 ? B0 : sel == 1 ? B1 : B2;
    float* C = sel == 0 ? C0 : sel == 1 ? C1 : C2;

    const int tid = threadIdx.x;
    const int lane = tid & 31;
    const int wid = tid >> 5;
    const int bm = blockIdx.y * 128;
    const int bn = (blockIdx.x & 15) * 128;
    const int wm = (wid >> 1) * 64;   // 0 or 64
    const int wn = (wid & 1) * 64;    // 0 or 64

    float acc[4][8][4];
#pragma unroll
    for (int i = 0; i < 4; i++)
#pragma unroll
        for (int j = 0; j < 8; j++)
#pragma unroll
            for (int r = 0; r < 4; r++) acc[i][j][r] = 0.f;

    // ldmatrix per-thread address components
    const int arow = lane & 15;
    const uint32_t ahalf = (uint32_t)((lane >> 4) << 4);        // 0 or 16
    const int brow = (lane & 7) | ((lane >> 4) << 3);
    const uint32_t bhalf = (uint32_t)(((lane >> 3) & 1) << 4);  // 0 or 16

    auto load_stage = [&](int s, int kt) {
        uint32_t base = sb + s * STAGEB;
        int k0 = kt * BKK;
#pragma unroll
        for (int i = 0; i < 4; i++) {
            int u = tid + i * 128;          // 0..511
            int r = u >> 2, c = u & 3;
            cp16(base + r * ROWA + c * 16, Ah + (size_t)(bm + r) * CC + k0 + c * 8);
        }
#pragma unroll
        for (int i = 0; i < 4; i++) {
            int u = tid + i * 128;          // 0..511
            int r = u >> 2, c = u & 3;
            cp16(base + ATILE_B + r * ROWA + c * 16, Bm + (size_t)(bn + r) * CC + k0 + c * 8);
        }
    };

    load_stage(0, 0); CP_COMMIT();
    load_stage(1, 1); CP_COMMIT();
    load_stage(2, 2); CP_COMMIT();

    for (int kt = 0; kt < KTILES; kt++) {
        if (kt <= KTILES - 3)      cp_wait<2>();
        else if (kt == KTILES - 2) cp_wait<1>();
        else                       cp_wait<0>();
        __syncthreads();
        if (kt + 3 < KTILES) { load_stage((kt + 3) % STAGES, kt + 3); CP_COMMIT(); }

        const uint32_t st = sb + (kt % STAGES) * STAGEB;
        const uint32_t aBase = st + (uint32_t)((wm + arow) * ROWA);
        const uint32_t bBase = st + ATILE_B + (uint32_t)((wn + brow) * ROWA);
#pragma unroll
        for (int ks = 0; ks < 2; ks++) {
            uint32_t ah[4][4];
            const uint32_t aoff = (uint32_t)(ks * 32) + ahalf;
#pragma unroll
            for (int mi = 0; mi < 4; mi++)
                ldsm4(ah[mi], aBase + mi * 16 * ROWA + aoff);
            const uint32_t boff = (uint32_t)(ks * 32) + bhalf;
#pragma unroll
            for (int jj = 0; jj < 4; jj++) {
                uint32_t bh[4];
                ldsm4(bh, bBase + jj * 16 * ROWA + boff);
#pragma unroll
                for (int mi = 0; mi < 4; mi++) {
                    mma_f16(acc[mi][2*jj],   ah[mi], bh);
                    mma_f16(acc[mi][2*jj+1], ah[mi], bh + 2);
                }
            }
        }
    }

    const int gr = lane >> 2, ti = lane & 3;

    if (EPI == 2) {
        // fused row-norm epilogue: per-row sum/sumsq over the 128-col tile
        float rs[8], rq[8];
#pragma unroll
        for (int mi = 0; mi < 4; mi++) {
#pragma unroll
            for (int half = 0; half < 2; half++) {
                float s = 0.f, ss = 0.f;
#pragma unroll
                for (int j = 0; j < 8; j++) {
                    float a0 = acc[mi][j][half*2+0], a1 = acc[mi][j][half*2+1];
                    s += a0 + a1; ss += a0*a0 + a1*a1;
                }
                rs[mi*2+half] = s; rq[mi*2+half] = ss;
            }
        }
#pragma unroll
        for (int o = 1; o <= 2; o <<= 1) {
#pragma unroll
            for (int t = 0; t < 8; t++) {
                rs[t] += __shfl_xor_sync(0xFFFFFFFFu, rs[t], o);
                rq[t] += __shfl_xor_sync(0xFFFFFFFFu, rq[t], o);
            }
        }
        float* ssum = (float*)smem;         // [128][2]
        float* sss  = ssum + 256;           // [128][2]
        __syncthreads();
        if (ti == 0) {
#pragma unroll
            for (int t = 0; t < 8; t++) {
                int row = wm + (t >> 1) * 16 + (t & 1) * 8 + gr;
                int wc = wid & 1;
                ssum[row * 2 + wc] = rs[t];
                sss [row * 2 + wc] = rq[t];
            }
        }
        __syncthreads();
#pragma unroll
        for (int mi = 0; mi < 4; mi++) {
#pragma unroll
            for (int half = 0; half < 2; half++) {
                int row = wm + mi * 16 + half * 8 + gr;
                int m0 = bm + row;
                float S = ssum[row*2] + ssum[row*2+1];
                float Q = sss [row*2] + sss [row*2+1];
                if (sel < 2) {
                    float inv = 1.f / fmaxf(sqrtf(Q), 1e-12f);
#pragma unroll
                    for (int j = 0; j < 8; j++) {
                        int col = bn + wn + j * 8 + ti * 2;
                        float2 v = make_float2(acc[mi][j][half*2] * inv,
                                               acc[mi][j][half*2+1] * inv);
                        *(float2*)(C + (size_t)m0 * CC + col) = v;
                    }
                } else {
                    float mean = S * (1.f / 128.f);
                    float rr = rsqrtf(Q * (1.f / 128.f) - mean * mean + 1e-5f);
#pragma unroll
                    for (int j = 0; j < 8; j++) {
                        int d = wn + j * 8 + ti * 2;
                        int col = bn + d;
                        float2 v;
                        v.x = (acc[mi][j][half*2]   - mean) * rr * bias0[d]   + bias1[d];
                        v.y = (acc[mi][j][half*2+1] - mean) * rr * bias0[d+1] + bias1[d+1];
                        *(float2*)(C + (size_t)m0 * CC + col) = v;
                    }
                }
            }
        }
    } else if (EPI == 1 && sel == 2) {
        // gamma tile: only cols 0-15 are real (gamma_w zero-padded)
        if (wn == 0) {
#pragma unroll
            for (int mi = 0; mi < 4; mi++) {
                int m0 = bm + wm + mi * 16 + gr;
#pragma unroll
                for (int j = 0; j < 2; j++) {
                    int col = j * 8 + ti * 2;          // 0..14
                    float g0a = sigmoidf(acc[mi][j][0] + bias2[col]);
                    float g0b = sigmoidf(acc[mi][j][1] + bias2[col + 1]);
                    float g1a = sigmoidf(acc[mi][j][2] + bias2[col]);
                    float g1b = sigmoidf(acc[mi][j][3] + bias2[col + 1]);
                    *(float2*)(g_gamma + (size_t)m0 * HH + col) = make_float2(g0a, g0b);
                    *(float2*)(g_gamma + (size_t)(m0 + 8) * HH + col) = make_float2(g1a, g1b);
                }
            }
        }
    } else {
        const float* bias = (sel == 0) ? bias0 : bias1;
#pragma unroll
        for (int mi = 0; mi < 4; mi++) {
            int m0 = bm + wm + mi * 16 + gr;
#pragma unroll
            for (int j = 0; j < 8; j++) {
                int col = bn + wn + j * 8 + ti * 2;
                float2 v0 = make_float2(acc[mi][j][0], acc[mi][j][1]);
                float2 v1 = make_float2(acc[mi][j][2], acc[mi][j][3]);
                if (EPI == 1) {
                    float b0 = bias[col], b1 = bias[col + 1];
                    v0.x = sigmoidf(v0.x + b0); v0.y = sigmoidf(v0.y + b1);
                    v1.x = sigmoidf(v1.x + b0); v1.y = sigmoidf(v1.y + b1);
                }
                *(float2*)(C + (size_t)m0 * CC + col) = v0;
                *(float2*)(C + (size_t)(m0 + 8) * CC + col) = v1;
            }
        }
    }
}

// ------- causal depthwise conv (K=4) + SiLU + fp16 casts (xc and x) --------
__global__ void conv_silu_kernel(const float* __restrict__ x,
                                 const float* __restrict__ w,
                                 const float* __restrict__ b) {
    int idx = blockIdx.x * blockDim.x + threadIdx.x;
    if (idx >= NTOT) return;
    int c = idx & (CC - 1);
    int t = (idx / CC) & (TT - 1);
    float acc = b[c];
    const float* wc = w + c * KK;
    float xcur = 0.f;
#pragma unroll
    for (int j = 0; j < KK; j++) {
        int tt = t - (KK - 1) + j;
        if (tt >= 0) {
            float xv = x[idx + (j - (KK - 1)) * CC];
            if (j == KK - 1) xcur = xv;
            acc = fmaf(xv, wc[j], acc);
        }
    }
    float y = acc * sigmoidf(acc);
    g_ch[idx] = __float2half(y);
    g_xh[idx] = __float2half(xcur);
}

// ------- chunked scan pass A: kv = ig*k*v inline + local scan --------------
__global__ void scan_local_kernel() {
    int blk = blockIdx.x;
    int chunk = blk & (NCH - 1);
    int bh = blk / NCH;
    int b = bh / HH, h = bh % HH;
    int d = threadIdx.x;
    int t0 = chunk * CHL;
    size_t idx = ((size_t)(b * TT + t0) * HH + h) * DD + d;
    const float* gam = g_gamma + (size_t)(b * TT + t0) * HH + h;
    float* cumg = g_cumG + (size_t)bh * TT + t0;
    float mem = 0.f, cg = 1.f;
#pragma unroll 4
    for (int tt = 0; tt < CHL; tt++) {
        float g = __ldg(gam + (size_t)tt * HH);
        float kv = g_ig[idx] * g_k[idx] * g_v[idx];
        mem = fmaf(g, mem, kv);
        g_v[idx] = mem;
        cg *= g;
        if (d == 0) cumg[tt] = cg;
        idx += (size_t)HH * DD;
    }
    g_carry[(size_t)blk * DD + d] = mem;
}

// ---------------- chunked scan: pass B (combine carries) -------------------
__global__ void scan_carry_kernel() {
    int bh = blockIdx.x;
    int d = threadIdx.x;
    float p = 0.f;
    for (int c = 0; c < NCH; c++) {
        g_prefix[((size_t)bh * NCH + c) * DD + d] = p;
        float G = g_cumG[(size_t)bh * TT + c * CHL + CHL - 1];
        p = g_carry[((size_t)bh * NCH + c) * DD + d] + G * p;
    }
}

// -------- prefix apply + LN(mem)*q -> GroupNorm -> *og -> fp16 cast --------
__global__ void post_kernel(const float* __restrict__ mn_g, const float* __restrict__ mn_b,
                            const float* __restrict__ gn_g, const float* __restrict__ gn_b) {
    int row = (blockIdx.x * blockDim.x + threadIdx.x) >> 5;
    int lane = threadIdx.x & 31;
    if (row >= NTOK * HH) return;
    size_t off = (size_t)row * DD + lane * 4;
    float4 m  = *(const float4*)(g_v + off);
    float4 q  = *(const float4*)(g_q + off);
    float4 og = *(const float4*)(g_og + off);

    int b = row / (TT * HH);
    int t = (row / HH) & (TT - 1);
    int h = row & (HH - 1);
    int bh = b * HH + h;
    int chunk = t / CHL;
    float cg = g_cumG[(size_t)bh * TT + t];
    float4 pf = *(const float4*)(g_prefix + ((size_t)bh * NCH + chunk) * DD + lane * 4);
    m.x = fmaf(pf.x, cg, m.x);
    m.y = fmaf(pf.y, cg, m.y);
    m.z = fmaf(pf.z, cg, m.z);
    m.w = fmaf(pf.w, cg, m.w);

    float s = m.x + m.y + m.z + m.w;
    float ss = m.x * m.x + m.y * m.y + m.z * m.z + m.w * m.w;
    s = warp_sum(s); ss = warp_sum(ss);
    float mean = s * (1.f / DD);
    float var = ss * (1.f / DD) - mean * mean;
    float r = rsqrtf(var + 1e-5f);
    int d = lane * 4;
    float4 o1;
    o1.x = ((m.x - mean) * r * mn_g[d + 0] + mn_b[d + 0]) * q.x;
    o1.y = ((m.y - mean) * r * mn_g[d + 1] + mn_b[d + 1]) * q.y;
    o1.z = ((m.z - mean) * r * mn_g[d + 2] + mn_b[d + 2]) * q.z;
    o1.w = ((m.w - mean) * r * mn_g[d + 3] + mn_b[d + 3]) * q.w;

    float s2 = o1.x + o1.y + o1.z + o1.w;
    float ss2 = o1.x * o1.x + o1.y * o1.y + o1.z * o1.z + o1.w * o1.w;
    s2 = warp_sum(s2); ss2 = warp_sum(ss2);
    float mean2 = s2 * (1.f / DD);
    float var2 = ss2 * (1.f / DD) - mean2 * mean2;
    float r2 = rsqrtf(var2 + 1e-5f);
    int c = h * DD + d;
    float ov0 = (((o1.x - mean2) * r2) * gn_g[c + 0] + gn_b[c + 0]) * og.x;
    float ov1 = (((o1.y - mean2) * r2) * gn_g[c + 1] + gn_b[c + 1]) * og.y;
    float ov2 = (((o1.z - mean2) * r2) * gn_g[c + 2] + gn_b[c + 2]) * og.z;
    float ov3 = (((o1.w - mean2) * r2) * gn_g[c + 3] + gn_b[c + 3]) * og.w;
    __half2* dst = (__half2*)(g_oh + off);
    dst[0] = __floats2half2_rn(ov0, ov1);
    dst[1] = __floats2half2_rn(ov2, ov3);
}

// ---------------- launch ----------------------------------------------------
extern "C" void kernel_launch(void* const* d_in, const int* in_sizes, int n_in,
                              void* d_out, int out_size) {
    const float* x       = (const float*)d_in[0];
    const float* Wq      = (const float*)d_in[1];
    const float* Wk      = (const float*)d_in[2];
    const float* Wv      = (const float*)d_in[3];
    const float* Wo      = (const float*)d_in[4];
    const float* conv_w  = (const float*)d_in[5];
    const float* conv_b  = (const float*)d_in[6];
    const float* ig_w    = (const float*)d_in[7];
    const float* ig_b    = (const float*)d_in[8];
    const float* og_w    = (const float*)d_in[9];
    const float* og_b    = (const float*)d_in[10];
    const float* gamma_w = (const float*)d_in[11];
    const float* gamma_b = (const float*)d_in[12];
    const float* vn_g    = (const float*)d_in[13];
    const float* vn_b    = (const float*)d_in[14];
    const float* gn_g    = (const float*)d_in[15];
    const float* gn_b    = (const float*)d_in[16];
    const float* mn_g    = (const float*)d_in[17];
    const float* mn_b    = (const float*)d_in[18];
    float* out = (float*)d_out;

    float *p_q, *p_k, *p_v, *p_ig, *p_og;
    cudaGetSymbolAddress((void**)&p_q,  g_q);
    cudaGetSymbolAddress((void**)&p_k,  g_k);
    cudaGetSymbolAddress((void**)&p_v,  g_v);
    cudaGetSymbolAddress((void**)&p_ig, g_ig);
    cudaGetSymbolAddress((void**)&p_og, g_og);

    __half *p_xh, *p_ch, *p_oh, *p_wh, *p_gw;
    cudaGetSymbolAddress((void**)&p_xh, g_xh);
    cudaGetSymbolAddress((void**)&p_ch, g_ch);
    cudaGetSymbolAddress((void**)&p_oh, g_oh);
    cudaGetSymbolAddress((void**)&p_wh, g_wh);
    cudaGetSymbolAddress((void**)&p_gw, g_gwpad);

    cudaFuncSetAttribute((const void*)gemm_multi<0>, cudaFuncAttributeMaxDynamicSharedMemorySize, GEMM_SMEM);
    cudaFuncSetAttribute((const void*)gemm_multi<1>, cudaFuncAttributeMaxDynamicSharedMemorySize, GEMM_SMEM);
    cudaFuncSetAttribute((const void*)gemm_multi<2>, cudaFuncAttributeMaxDynamicSharedMemorySize, GEMM_SMEM);

    const size_t WSZ = (size_t)CC * CC;   // 4M elems per weight matrix

    // side stream + events for forked capture (created per call; few calls)
    cudaStream_t s1;
    cudaStreamCreateWithFlags(&s1, cudaStreamNonBlocking);
    cudaEvent_t e0, eW, eConv, eJoin;
    cudaEventCreateWithFlags(&e0,    cudaEventDisableTiming);
    cudaEventCreateWithFlags(&eW,    cudaEventDisableTiming);
    cudaEventCreateWithFlags(&eConv, cudaEventDisableTiming);
    cudaEventCreateWithFlags(&eJoin, cudaEventDisableTiming);

    // fork: weight conversions on s1 parallel with conv on default stream
    cudaEventRecord(e0, 0);
    cudaStreamWaitEvent(s1, e0, 0);
    cvt_w_kernel<<<(6 * (int)WSZ) / 256, 256, 0, s1>>>(Wq, Wk, Wv, ig_w, og_w, Wo);
    cvt_gw_kernel<<<(128 * CC) / 256, 256, 0, s1>>>(gamma_w);
    cudaEventRecord(eW, s1);

    conv_silu_kernel<<<NTOT / 256, 256>>>(x, conv_w, conv_b);
    cudaEventRecord(eConv, 0);

    // qkv on stream 0 (needs conv + cvt_w)
    cudaStreamWaitEvent(0, eW, 0);
    {
        dim3 grid(48, NTOK / 128);
        gemm_multi<2><<<grid, 128, GEMM_SMEM>>>(p_xh,
            p_wh + 0*WSZ, p_wh + 1*WSZ, p_wh + 2*WSZ,
            p_q, p_k, p_v, vn_g, vn_b, nullptr);
    }

    // ig/og + gamma tile fused, on s1 overlapping qkv
    cudaStreamWaitEvent(s1, eConv, 0);
    {
        dim3 grid(33, NTOK / 128);   // tiles 0-15: ig, 16-31: og, 32: gamma
        gemm_multi<1><<<grid, 128, GEMM_SMEM, s1>>>(p_ch,
            p_wh + 3*WSZ, p_wh + 4*WSZ, p_gw,
            p_ig, p_og, nullptr, ig_b, og_b, gamma_b);
    }
    cudaEventRecord(eJoin, s1);
    cudaStreamWaitEvent(0, eJoin, 0);

    scan_local_kernel<<<BB * HH * NCH, DD>>>();
    scan_carry_kernel<<<BB * HH, DD>>>();

    int nrows = NTOK * HH;                       // 131072 rows of 128
    int rblocks = nrows / 8;
    post_kernel<<<rblocks, 256>>>(mn_g, mn_b, gn_g, gn_b);

    // final projection
    {
        dim3 grid(16, NTOK / 128);
        gemm_multi<0><<<grid, 128, GEMM_SMEM>>>(p_oh,
            p_wh + 5*WSZ, p_wh + 5*WSZ, p_wh + 5*WSZ,
            out, out, out, nullptr, nullptr, nullptr);
    }
}